// round 5
// baseline (speedup 1.0000x reference)
#include <cuda_runtime.h>
#include <cuda_fp16.h>
#include <cstdint>

#define K_DIM 1024
#define N_DIM 1024
#define MAX_M 65536

// ---------------------------------------------------------------------------
// Scratch (device globals — no allocation APIs allowed)
// ---------------------------------------------------------------------------
__device__ __half g_A[(size_t)MAX_M * K_DIM];
__device__ __half g_B[(size_t)N_DIM * K_DIM];

__device__ __forceinline__ uint32_t smem_u32(const void* p) {
    uint32_t a;
    asm("{ .reg .u64 t; cvta.to.shared.u64 t, %1; cvt.u32.u64 %0, t; }"
        : "=r"(a) : "l"(p));
    return a;
}

__device__ __forceinline__ void cp_async16(uint32_t saddr, const void* gaddr) {
    asm volatile("cp.async.cg.shared.global [%0], [%1], 16;"
                 :: "r"(saddr), "l"(gaddr) : "memory");
}

__device__ __forceinline__ void ldsm_x4(uint32_t addr, uint32_t& r0, uint32_t& r1,
                                        uint32_t& r2, uint32_t& r3) {
    asm volatile("ldmatrix.sync.aligned.m8n8.x4.shared.b16 {%0,%1,%2,%3}, [%4];"
                 : "=r"(r0), "=r"(r1), "=r"(r2), "=r"(r3) : "r"(addr));
}

__device__ __forceinline__ void mma16816(float* c, const uint32_t* a,
                                         const uint32_t* b) {
    asm volatile(
        "mma.sync.aligned.m16n8k16.row.col.f32.f16.f16.f32 "
        "{%0,%1,%2,%3}, {%4,%5,%6,%7}, {%8,%9}, {%0,%1,%2,%3};"
        : "+f"(c[0]), "+f"(c[1]), "+f"(c[2]), "+f"(c[3])
        : "r"(a[0]), "r"(a[1]), "r"(a[2]), "r"(a[3]), "r"(b[0]), "r"(b[1]));
}

// ---------------------------------------------------------------------------
// Kernel 1: per-row logmap0 scale fused with fp16 convert of A.
// ---------------------------------------------------------------------------
__global__ void convertA_kernel(const float* __restrict__ x) {
    const int row = blockIdx.x;
    const int t = threadIdx.x;
    const float4* xr = reinterpret_cast<const float4*>(x + ((size_t)row << 10));
    float4 v = xr[t];
    v.x = (v.x == v.x) ? v.x : 0.0f;
    v.y = (v.y == v.y) ? v.y : 0.0f;
    v.z = (v.z == v.z) ? v.z : 0.0f;
    v.w = (v.w == v.w) ? v.w : 0.0f;

    float ss = v.x * v.x + v.y * v.y + v.z * v.z + v.w * v.w;
#pragma unroll
    for (int o = 16; o > 0; o >>= 1) ss += __shfl_down_sync(0xFFFFFFFFu, ss, o);
    __shared__ float ws[8];
    __shared__ float s_scale;
    if ((t & 31) == 0) ws[t >> 5] = ss;
    __syncthreads();
    if (t == 0) {
        float tt = 0.0f;
#pragma unroll
        for (int w = 0; w < 8; w++) tt += ws[w];
        float pn = fmaxf(sqrtf(tt), 1e-15f);
        float arg = fminf(pn, 0.99f - 1e-7f);
        arg = fmaxf(arg, -0.99f + 1e-7f);
        float at = 0.5f * (log1pf(arg) - log1pf(-arg));
        s_scale = at / pn;
    }
    __syncthreads();
    const float s = s_scale;

    float a[4] = {v.x, v.y, v.z, v.w};
    __half h[4];
#pragma unroll
    for (int i = 0; i < 4; i++) {
        float w = fminf(fmaxf(a[i] * s, -50.0f), 50.0f);
        h[i] = __float2half_rn(w);
    }
    __half2* ph = reinterpret_cast<__half2*>(g_A + ((size_t)row << 10));
    ph[2 * t]     = __halves2half2(h[0], h[1]);
    ph[2 * t + 1] = __halves2half2(h[2], h[3]);
}

// ---------------------------------------------------------------------------
// Kernel 2: fp16 convert of m (1024x1024).
// ---------------------------------------------------------------------------
__global__ void convertB_kernel(const float* __restrict__ m) {
    const size_t i = (size_t)blockIdx.x * 256 + threadIdx.x;  // 262144 float4s
    float4 v = reinterpret_cast<const float4*>(m)[i];
    __half2* ph = reinterpret_cast<__half2*>(g_B);
    ph[2 * i]     = __halves2half2(__float2half_rn(v.x), __float2half_rn(v.y));
    ph[2 * i + 1] = __halves2half2(__float2half_rn(v.z), __float2half_rn(v.w));
}

// ---------------------------------------------------------------------------
// Kernel 3: fp16 HMMA GEMM, CTA tile 256x256, BK=64, 512 threads (16 warps,
// 4m x 4n grid of 64x64 warp tiles). 3-stage cp.async pipeline, 64 KB/stage
// (A 256x128B + B 256x128B, SW128 swizzle) = 192 KB SMEM, 1 CTA/SM.
// ---------------------------------------------------------------------------
#define TILE_B 32768
#define STAGE_B (2 * TILE_B)
#define NSTAGE 3
#define SMEM_TOTAL (NSTAGE * STAGE_B)   // 192 KB

__global__ __launch_bounds__(512, 1) void gemm_hmma(float* __restrict__ C) {
    extern __shared__ char smem[];
    const uint32_t sb = smem_u32(smem);
    const int tid = threadIdx.x;
    const int wid = tid >> 5, lid = tid & 31;
    const int wm = wid & 3, wn = wid >> 2;        // warp grid 4(m) x 4(n)
    const int bm = blockIdx.y << 8, bn = blockIdx.x << 8;

    auto load_stage = [&](int st, int k0) {
        const uint32_t sbase = sb + st * STAGE_B;
#pragma unroll
        for (int t = 0; t < 2; t++) {
            const __half* g = t ? g_B : g_A;
            const int rb = t ? bn : bm;
            const uint32_t sdst = sbase + t * TILE_B;
#pragma unroll
            for (int i = 0; i < 4; i++) {
                int idx = tid + (i << 9);           // 0..2047
                int r = idx >> 3;                   // 0..255
                int c16 = idx & 7;                  // 16B chunk in row
                uint32_t boff = (uint32_t)((r << 7) + (c16 << 4));
                uint32_t sw = boff ^ ((boff >> 3) & 0x70);
                cp_async16(sdst + sw,
                           g + ((size_t)(rb + r) << 10) + k0 + (c16 << 3));
            }
        }
        asm volatile("cp.async.commit_group;" ::: "memory");
    };

    // ldmatrix lane addressing (proven rounds 3-4).
    const int lr = lid & 15;
    const uint32_t khalf = (uint32_t)((lid >> 4) << 4);
    uint32_t rA[4], xA[4], rB[4], xB[4];
#pragma unroll
    for (int i = 0; i < 4; i++) {
        int r = wm * 64 + i * 16 + lr;
        rA[i] = (uint32_t)(r << 7);
        xA[i] = (uint32_t)((r & 7) << 4);
    }
#pragma unroll
    for (int j = 0; j < 4; j++) {
        int r = wn * 64 + j * 16 + lr;
        rB[j] = (uint32_t)(r << 7);
        xB[j] = (uint32_t)((r & 7) << 4);
    }

    float acc[4][8][4];
#pragma unroll
    for (int i = 0; i < 4; i++)
#pragma unroll
        for (int j = 0; j < 8; j++)
#pragma unroll
            for (int q = 0; q < 4; q++) acc[i][j][q] = 0.0f;

    load_stage(0, 0);
    load_stage(1, 64);

    int st = 0;
    for (int c = 0; c < 16; ++c) {
        if (c < 15) {
            asm volatile("cp.async.wait_group 1;" ::: "memory");
        } else {
            asm volatile("cp.async.wait_group 0;" ::: "memory");
        }
        __syncthreads();
        if (c + 2 < 16) {
            int st2 = st + 2; if (st2 >= NSTAGE) st2 -= NSTAGE;
            load_stage(st2, (c + 2) << 6);
        }

        const uint32_t tA = sb + st * STAGE_B;
        const uint32_t tB = tA + TILE_B;

#pragma unroll
        for (int kk = 0; kk < 4; kk++) {
            const uint32_t kb = (uint32_t)(kk * 32) + khalf;

            uint32_t a[4][4];
#pragma unroll
            for (int i = 0; i < 4; i++)
                ldsm_x4(tA + rA[i] + (kb ^ xA[i]),
                        a[i][0], a[i][1], a[i][2], a[i][3]);
            uint32_t b[8][2];
#pragma unroll
            for (int j = 0; j < 4; j++) {
                uint32_t r0, r1, r2, r3;
                ldsm_x4(tB + rB[j] + (kb ^ xB[j]), r0, r1, r2, r3);
                b[2 * j][0] = r0; b[2 * j + 1][0] = r1;
                b[2 * j][1] = r2; b[2 * j + 1][1] = r3;
            }
#pragma unroll
            for (int i = 0; i < 4; i++)
#pragma unroll
                for (int j = 0; j < 8; j++) mma16816(acc[i][j], a[i], b[j]);
        }

        st = st + 1; if (st >= NSTAGE) st = 0;
    }

    // Store with mx clip to ±1000.
    const int r0 = bm + wm * 64 + (lid >> 2);
    const int c0 = bn + wn * 64 + ((lid & 3) << 1);
#pragma unroll
    for (int i = 0; i < 4; i++) {
#pragma unroll
        for (int j = 0; j < 8; j++) {
            float2 p0, p1;
            p0.x = fminf(fmaxf(acc[i][j][0], -1000.0f), 1000.0f);
            p0.y = fminf(fmaxf(acc[i][j][1], -1000.0f), 1000.0f);
            p1.x = fminf(fmaxf(acc[i][j][2], -1000.0f), 1000.0f);
            p1.y = fminf(fmaxf(acc[i][j][3], -1000.0f), 1000.0f);
            size_t base = ((size_t)(r0 + i * 16) << 10) + c0 + j * 8;
            *reinterpret_cast<float2*>(C + base) = p0;
            *reinterpret_cast<float2*>(C + base + (8 << 10)) = p1;
        }
    }
}

// ---------------------------------------------------------------------------
// Kernel 4 (in-place): out = proj(expmap0(mx, 1), 1)
// ---------------------------------------------------------------------------
__global__ void epilogue_kernel(float* __restrict__ C) {
    const int row = blockIdx.x;
    float4* p = reinterpret_cast<float4*>(C + ((size_t)row << 10));
    float4 v = p[threadIdx.x];

    float ss = v.x * v.x + v.y * v.y + v.z * v.z + v.w * v.w;
#pragma unroll
    for (int o = 16; o > 0; o >>= 1) ss += __shfl_down_sync(0xFFFFFFFFu, ss, o);
    __shared__ float wsum[8];
    __shared__ float total_s;
    if ((threadIdx.x & 31) == 0) wsum[threadIdx.x >> 5] = ss;
    __syncthreads();
    if (threadIdx.x == 0) {
        float t = 0.0f;
#pragma unroll
        for (int w = 0; w < 8; w++) t += wsum[w];
        total_s = t;
    }
    __syncthreads();

    const float un = fmaxf(sqrtf(total_s), 1e-15f);
    const float th = tanhf(un);
    float f = th / un;
    const float max_norm = (float)(1.0 - 1e-10);
    if (th > max_norm) f *= max_norm / fmaxf(th, 1e-9f);

    v.x *= f; v.y *= f; v.z *= f; v.w *= f;
    p[threadIdx.x] = v;
}

// ---------------------------------------------------------------------------
extern "C" void kernel_launch(void* const* d_in, const int* in_sizes, int n_in,
                              void* d_out, int out_size) {
    const float* x = (const float*)d_in[0];   // [M, 1024]
    const float* m = (const float*)d_in[1];   // [1024, 1024]
    float* out = (float*)d_out;               // [M, 1024] f32

    int M = in_sizes[0] / K_DIM;
    if (M > MAX_M) M = MAX_M;

    cudaFuncSetAttribute(gemm_hmma, cudaFuncAttributeMaxDynamicSharedMemorySize,
                         SMEM_TOTAL);

    convertA_kernel<<<M, 256>>>(x);
    convertB_kernel<<<1024, 256>>>(m);

    dim3 grid(N_DIM / 256, M / 256);
    gemm_hmma<<<grid, 512, SMEM_TOTAL>>>(out);

    epilogue_kernel<<<M, 256>>>(out);
}

// round 6
// speedup vs baseline: 2.2264x; 2.2264x over previous
#include <cuda_runtime.h>
#include <cuda_fp16.h>
#include <cstdint>

#define K_DIM 1024
#define N_DIM 1024
#define MAX_M 65536

// ---------------------------------------------------------------------------
// Scratch (device globals — no allocation APIs allowed)
// ---------------------------------------------------------------------------
__device__ __half g_A[(size_t)MAX_M * K_DIM];
__device__ __half g_B[(size_t)N_DIM * K_DIM];

__device__ __forceinline__ uint32_t smem_u32(const void* p) {
    uint32_t a;
    asm("{ .reg .u64 t; cvta.to.shared.u64 t, %1; cvt.u32.u64 %0, t; }"
        : "=r"(a) : "l"(p));
    return a;
}

__device__ __forceinline__ void cp_async16(uint32_t saddr, const void* gaddr) {
    asm volatile("cp.async.cg.shared.global [%0], [%1], 16;"
                 :: "r"(saddr), "l"(gaddr) : "memory");
}

__device__ __forceinline__ void ldsm_x4(uint32_t addr, uint32_t& r0, uint32_t& r1,
                                        uint32_t& r2, uint32_t& r3) {
    asm volatile("ldmatrix.sync.aligned.m8n8.x4.shared.b16 {%0,%1,%2,%3}, [%4];"
                 : "=r"(r0), "=r"(r1), "=r"(r2), "=r"(r3) : "r"(addr));
}

__device__ __forceinline__ void mma16816(float* c, const uint32_t* a,
                                         const uint32_t* b) {
    asm volatile(
        "mma.sync.aligned.m16n8k16.row.col.f32.f16.f16.f32 "
        "{%0,%1,%2,%3}, {%4,%5,%6,%7}, {%8,%9}, {%0,%1,%2,%3};"
        : "+f"(c[0]), "+f"(c[1]), "+f"(c[2]), "+f"(c[3])
        : "r"(a[0]), "r"(a[1]), "r"(a[2]), "r"(a[3]), "r"(b[0]), "r"(b[1]));
}

// ---------------------------------------------------------------------------
// Kernel 1: per-row logmap0 scale fused with fp16 convert of A.
// One block (256 threads) per row; each thread owns one float4.
// ---------------------------------------------------------------------------
__global__ void convertA_kernel(const float* __restrict__ x) {
    const int row = blockIdx.x;
    const int t = threadIdx.x;
    const float4* xr = reinterpret_cast<const float4*>(x + ((size_t)row << 10));
    float4 v = xr[t];
    v.x = (v.x == v.x) ? v.x : 0.0f;
    v.y = (v.y == v.y) ? v.y : 0.0f;
    v.z = (v.z == v.z) ? v.z : 0.0f;
    v.w = (v.w == v.w) ? v.w : 0.0f;

    float ss = v.x * v.x + v.y * v.y + v.z * v.z + v.w * v.w;
#pragma unroll
    for (int o = 16; o > 0; o >>= 1) ss += __shfl_down_sync(0xFFFFFFFFu, ss, o);
    __shared__ float ws[8];
    __shared__ float s_scale;
    if ((t & 31) == 0) ws[t >> 5] = ss;
    __syncthreads();
    if (t == 0) {
        float tt = 0.0f;
#pragma unroll
        for (int w = 0; w < 8; w++) tt += ws[w];
        float pn = fmaxf(sqrtf(tt), 1e-15f);
        float arg = fminf(pn, 0.99f - 1e-7f);
        arg = fmaxf(arg, -0.99f + 1e-7f);
        float at = 0.5f * (log1pf(arg) - log1pf(-arg));
        s_scale = at / pn;
    }
    __syncthreads();
    const float s = s_scale;

    float a[4] = {v.x, v.y, v.z, v.w};
    __half h[4];
#pragma unroll
    for (int i = 0; i < 4; i++) {
        float w = fminf(fmaxf(a[i] * s, -50.0f), 50.0f);
        h[i] = __float2half_rn(w);
    }
    __half2* ph = reinterpret_cast<__half2*>(g_A + ((size_t)row << 10));
    ph[2 * t]     = __halves2half2(h[0], h[1]);
    ph[2 * t + 1] = __halves2half2(h[2], h[3]);
}

// ---------------------------------------------------------------------------
// Kernel 2: fp16 convert of m (1024x1024).
// ---------------------------------------------------------------------------
__global__ void convertB_kernel(const float* __restrict__ m) {
    const size_t i = (size_t)blockIdx.x * 256 + threadIdx.x;  // 262144 float4s
    float4 v = reinterpret_cast<const float4*>(m)[i];
    __half2* ph = reinterpret_cast<__half2*>(g_B);
    ph[2 * i]     = __halves2half2(__float2half_rn(v.x), __float2half_rn(v.y));
    ph[2 * i + 1] = __halves2half2(__float2half_rn(v.z), __float2half_rn(v.w));
}

// ---------------------------------------------------------------------------
// Kernel 3: single-pass fp16 HMMA GEMM (fp32 accumulate) — round-4 proven
// config. CTA tile 128x128, BK=64, 8 warps (4m x 2n). 3-stage cp.async
// pipeline, 32 KB/stage, 96 KB SMEM, 2 CTAs/SM (regs must stay <= 128).
// ---------------------------------------------------------------------------
#define TILE_B 16384
#define STAGE_B (2 * TILE_B)
#define NSTAGE 3
#define SMEM_TOTAL (NSTAGE * STAGE_B)   // 96 KB

__global__ __launch_bounds__(256, 2) void gemm_hmma(float* __restrict__ C) {
    extern __shared__ char smem[];
    const uint32_t sb = smem_u32(smem);
    const int tid = threadIdx.x;
    const int wid = tid >> 5, lid = tid & 31;
    const int wm = wid & 3, wn = wid >> 2;        // warp grid 4(m) x 2(n)
    const int bm = blockIdx.y << 7, bn = blockIdx.x << 7;

    auto load_stage = [&](int st, int k0) {
        const uint32_t sbase = sb + st * STAGE_B;
#pragma unroll
        for (int t = 0; t < 2; t++) {
            const __half* g = t ? g_B : g_A;
            const int rb = t ? bn : bm;
            const uint32_t sdst = sbase + t * TILE_B;
#pragma unroll
            for (int i = 0; i < 4; i++) {
                int idx = tid + (i << 8);           // 0..1023
                int r = idx >> 3;                   // 0..127
                int c16 = idx & 7;                  // 16B chunk in row
                uint32_t boff = (uint32_t)((r << 7) + (c16 << 4));
                uint32_t sw = boff ^ ((boff >> 3) & 0x70);
                cp_async16(sdst + sw,
                           g + ((size_t)(rb + r) << 10) + k0 + (c16 << 3));
            }
        }
        asm volatile("cp.async.commit_group;" ::: "memory");
    };

    const int lr = lid & 15;
    const uint32_t khalf = (uint32_t)((lid >> 4) << 4);
    uint32_t rA[2], xA[2], rB[4], xB[4];
#pragma unroll
    for (int i = 0; i < 2; i++) {
        int r = wm * 32 + i * 16 + lr;
        rA[i] = (uint32_t)(r << 7);
        xA[i] = (uint32_t)((r & 7) << 4);
    }
#pragma unroll
    for (int j = 0; j < 4; j++) {
        int r = wn * 64 + j * 16 + lr;
        rB[j] = (uint32_t)(r << 7);
        xB[j] = (uint32_t)((r & 7) << 4);
    }

    float acc[2][8][4];
#pragma unroll
    for (int i = 0; i < 2; i++)
#pragma unroll
        for (int j = 0; j < 8; j++)
#pragma unroll
            for (int q = 0; q < 4; q++) acc[i][j][q] = 0.0f;

    load_stage(0, 0);
    load_stage(1, 64);

    int st = 0;

    auto do_chunk = [&](int c) {
        const uint32_t stb = sb + st * STAGE_B;
        const uint32_t tA = stb, tB = stb + TILE_B;
#pragma unroll
        for (int kk = 0; kk < 4; kk++) {
            const uint32_t kb = (uint32_t)(kk * 32) + khalf;
            uint32_t a[2][4];
#pragma unroll
            for (int i = 0; i < 2; i++)
                ldsm_x4(tA + rA[i] + (kb ^ xA[i]),
                        a[i][0], a[i][1], a[i][2], a[i][3]);
            uint32_t b[8][2];
#pragma unroll
            for (int j = 0; j < 4; j++) {
                uint32_t r0, r1, r2, r3;
                ldsm_x4(tB + rB[j] + (kb ^ xB[j]), r0, r1, r2, r3);
                b[2 * j][0] = r0; b[2 * j + 1][0] = r1;
                b[2 * j][1] = r2; b[2 * j + 1][1] = r3;
            }
#pragma unroll
            for (int i = 0; i < 2; i++)
#pragma unroll
                for (int j = 0; j < 8; j++) mma16816(acc[i][j], a[i], b[j]);
        }
        st = st + 1; if (st >= NSTAGE) st = 0;
    };

    for (int c = 0; c < 15; ++c) {
        asm volatile("cp.async.wait_group 1;" ::: "memory");
        __syncthreads();
        if (c + 2 < 16) {
            int st2 = st + 2; if (st2 >= NSTAGE) st2 -= NSTAGE;
            load_stage(st2, (c + 2) << 6);
        }
        do_chunk(c);
    }
    asm volatile("cp.async.wait_group 0;" ::: "memory");
    __syncthreads();
    do_chunk(15);

    // Store raw fp32 mx (epilogue applies the ±1000 clip before use).
    const int r0 = bm + wm * 32 + (lid >> 2);
    const int c0 = bn + wn * 64 + ((lid & 3) << 1);
#pragma unroll
    for (int i = 0; i < 2; i++) {
#pragma unroll
        for (int j = 0; j < 8; j++) {
            size_t base = ((size_t)(r0 + i * 16) << 10) + c0 + j * 8;
            *reinterpret_cast<float2*>(C + base) =
                make_float2(acc[i][j][0], acc[i][j][1]);
            *reinterpret_cast<float2*>(C + base + (8 << 10)) =
                make_float2(acc[i][j][2], acc[i][j][3]);
        }
    }
}

// ---------------------------------------------------------------------------
// Kernel 4 (in-place): out = proj(expmap0(clip(mx), 1), 1)
// 512 threads per block, 2 rows per block (256 threads per row).
// ---------------------------------------------------------------------------
__global__ __launch_bounds__(512) void epilogue_kernel(float* __restrict__ C) {
    const int half = threadIdx.x >> 8;            // 0 or 1 (row within block)
    const int t = threadIdx.x & 255;
    const int row = (blockIdx.x << 1) + half;
    float4* p = reinterpret_cast<float4*>(C + ((size_t)row << 10));
    float4 v = __ldcs(&p[t]);
    v.x = fminf(fmaxf(v.x, -1000.0f), 1000.0f);
    v.y = fminf(fmaxf(v.y, -1000.0f), 1000.0f);
    v.z = fminf(fmaxf(v.z, -1000.0f), 1000.0f);
    v.w = fminf(fmaxf(v.w, -1000.0f), 1000.0f);

    float ss = v.x * v.x + v.y * v.y + v.z * v.z + v.w * v.w;
#pragma unroll
    for (int o = 16; o > 0; o >>= 1) ss += __shfl_down_sync(0xFFFFFFFFu, ss, o);
    __shared__ float wsum[2][8];
    __shared__ float total_s[2];
    if ((t & 31) == 0) wsum[half][t >> 5] = ss;
    __syncthreads();
    if (t == 0) {
        float tt = 0.0f;
#pragma unroll
        for (int w = 0; w < 8; w++) tt += wsum[half][w];
        total_s[half] = tt;
    }
    __syncthreads();

    const float un = fmaxf(sqrtf(total_s[half]), 1e-15f);
    const float th = tanhf(un);
    float f = th / un;
    const float max_norm = (float)(1.0 - 1e-10);
    if (th > max_norm) f *= max_norm / fmaxf(th, 1e-9f);

    v.x *= f; v.y *= f; v.z *= f; v.w *= f;
    __stcs(&p[t], v);
}

// ---------------------------------------------------------------------------
extern "C" void kernel_launch(void* const* d_in, const int* in_sizes, int n_in,
                              void* d_out, int out_size) {
    const float* x = (const float*)d_in[0];   // [M, 1024]
    const float* m = (const float*)d_in[1];   // [1024, 1024]
    float* out = (float*)d_out;               // [M, 1024] f32

    int M = in_sizes[0] / K_DIM;
    if (M > MAX_M) M = MAX_M;

    cudaFuncSetAttribute(gemm_hmma, cudaFuncAttributeMaxDynamicSharedMemorySize,
                         SMEM_TOTAL);

    convertA_kernel<<<M, 256>>>(x);
    convertB_kernel<<<1024, 256>>>(m);

    dim3 grid(N_DIM / 128, M / 128);
    gemm_hmma<<<grid, 256, SMEM_TOTAL>>>(out);

    epilogue_kernel<<<M / 2, 512>>>(out);
}